// round 5
// baseline (speedup 1.0000x reference)
#include <cuda_runtime.h>
#include <cuda_fp16.h>
#include <math.h>

#define N_NODES 100000
#define N_HID   256
#define N_EDGES 3200000

// ---- scratch in device globals (no allocation allowed) ----
__device__ int      g_out_deg[N_NODES];
__device__ float    g_hun[N_NODES];                     // unscaled dot
__device__ __half   g_h1h[N_NODES];                     // scaled, fp16 gather table
__device__ __align__(8) float2 g_aggcnt[N_NODES];       // {agg_sum, in_deg_count}
__device__ float    g_W1[N_HID];                        // W[:,1]
__device__ float    g_pe_s[N_HID];                      // pe_coff * pe(t+1)
__device__ float    g_pe_dot;
__device__ float    g_b1;
__device__ unsigned g_bar0, g_bar1;                     // grid-barrier counters

// K0: zero scratch + barrier counters, compute PE row, W1, pe_dot, b1
__global__ void k_init(const float* __restrict__ W,
                       const float* __restrict__ b,
                       const float* __restrict__ pe_coff,
                       const int*   __restrict__ t_ptr) {
    int i = blockIdx.x * blockDim.x + threadIdx.x;
    int stride = gridDim.x * blockDim.x;
    for (int j = i; j < N_NODES; j += stride) {
        g_out_deg[j] = 0;
        g_aggcnt[j]  = make_float2(0.0f, 0.0f);
    }
    if (i == 0) { g_bar0 = 0u; g_bar1 = 0u; }
    if (blockIdx.x == 0) {
        int c = threadIdx.x;               // 256 threads == N_HID
        float w1 = W[c * 2 + 1];
        g_W1[c] = w1;
        int t = *t_ptr;
        float pos  = (float)(t + 1);
        float coff = pe_coff[0];
        int even = c & ~1;
        float div = expf((float)even * (-logf(10000.0f) / (float)N_HID));
        float pe  = (c & 1) ? cosf(pos * div) : sinf(pos * div);
        float pes = coff * pe;
        g_pe_s[c] = pes;
        __shared__ float sred[256];
        sred[c] = pes * w1;
        __syncthreads();
        for (int s = 128; s > 0; s >>= 1) {
            if (c < s) sred[c] += sred[c + s];
            __syncthreads();
        }
        if (c == 0) {
            g_pe_dot = sred[0];
            g_b1 = b[1];
        }
    }
}

// K1 fused: interleaved block roles (1 edge block per 4 node blocks).
#define FUSED_GRID 15625
__global__ void k_fused(const float* __restrict__ input,
                        const int*   __restrict__ src) {
    int b = blockIdx.x;
    if (b % 5 == 0) {
        // ---- edge role: out-degree atomics ----
        int eb = b / 5;
        int i = eb * 256 + threadIdx.x;
        int4 s = make_int4(0, 0, 0, 0);
        bool act = (i < N_EDGES / 4);
        if (act) s = __ldcs(&((const int4*)src)[i]);   // streaming: don't pollute L2
        cudaGridDependencySynchronize();               // k_init zeroed counters
        if (act) {
            atomicAdd(&g_out_deg[s.x], 1);
            atomicAdd(&g_out_deg[s.y], 1);
            atomicAdd(&g_out_deg[s.z], 1);
            atomicAdd(&g_out_deg[s.w], 1);
        }
    } else {
        // ---- node role: unscaled dot(input[r], W1) ----
        int nb = b - (b / 5 + 1);            // 0..12499
        int warp_in_block = threadIdx.x >> 5;
        int lane = threadIdx.x & 31;
        int row = nb * 8 + warp_in_block;
        float4 v0 = make_float4(0, 0, 0, 0), v1 = v0;
        bool act = (row < N_NODES);
        if (act) {
            const float4* rowp = (const float4*)(input + (size_t)row * N_HID);
            v0 = rowp[lane];
            v1 = rowp[lane + 32];
        }
        cudaGridDependencySynchronize();               // g_W1 from k_init
        if (act) {
            const float4* w4 = (const float4*)g_W1;
            float4 w0 = w4[lane];
            float4 w1 = w4[lane + 32];
            float acc = v0.x * w0.x + v0.y * w0.y + v0.z * w0.z + v0.w * w0.w
                      + v1.x * w1.x + v1.y * w1.y + v1.z * w1.z + v1.w * w1.w;
#pragma unroll
            for (int o = 16; o > 0; o >>= 1)
                acc += __shfl_xor_sync(0xffffffffu, acc, o);
            if (lane == 0) g_hun[row] = acc;
        }
    }
}

// grid-wide barrier (all blocks resident: grid == #SMs, 1 block/SM)
__device__ __forceinline__ void grid_barrier(unsigned* ctr, unsigned nblocks) {
    __syncthreads();
    if (threadIdx.x == 0) {
        __threadfence();                               // release prior writes
        atomicAdd(ctr, 1u);
        while (*(volatile unsigned*)ctr < nblocks) __nanosleep(64);
    }
    __syncthreads();
    __threadfence();                                   // acquire
}

// K2 merged persistent kernel: scale -> barrier -> RED pass (+ L2 prefetch
// of input using idle DRAM bandwidth) -> barrier -> gated output from L2.
__global__ void __launch_bounds__(1024, 1)
k_aggout(const int* __restrict__ src, const int* __restrict__ dst,
         const float* __restrict__ input, float* __restrict__ out) {
    const int tid = threadIdx.x;
    const unsigned g = gridDim.x;
    const int nth = (int)g * 1024;
    const int gt  = blockIdx.x * 1024 + tid;

    cudaGridDependencySynchronize();                   // k_fused done

    // ---- phase 0: h table (fp16), scaled by out-degree norm ----
    for (int i = gt; i < N_NODES; i += nth) {
        float od = (float)max(g_out_deg[i], 1);
        g_h1h[i] = __float2half((g_hun[i] + g_pe_dot) * rsqrtf(od));
    }
    grid_barrier(&g_bar0, g);

    // ---- phase 1: edge RED pass ----
    const int n4 = N_EDGES / 4;
    const int per = (n4 + (int)g - 1) / (int)g;
    const int base = blockIdx.x * per;
    const int end = min(base + per, n4);
    const float one = 1.0f;
    for (int i = base + tid; i < end; i += 1024) {
        int4 s = __ldcs(&((const int4*)src)[i]);
        int4 d = __ldcs(&((const int4*)dst)[i]);
        float h0 = __half2float(__ldg(&g_h1h[s.x]));
        float h1 = __half2float(__ldg(&g_h1h[s.y]));
        float h2 = __half2float(__ldg(&g_h1h[s.z]));
        float h3 = __half2float(__ldg(&g_h1h[s.w]));
#define REDV2(p, h) asm volatile("red.global.add.v2.f32 [%0], {%1, %2};" :: "l"(p), "f"(h), "f"(one) : "memory")
        REDV2(&g_aggcnt[d.x], h0);
        REDV2(&g_aggcnt[d.y], h1);
        REDV2(&g_aggcnt[d.z], h2);
        REDV2(&g_aggcnt[d.w], h3);
#undef REDV2
    }

    // ---- prefetch this thread's phase-2 input slice into L2 (uses DRAM
    //      bandwidth that is idle while other blocks finish their REDs) ----
    const long long total4 = (long long)N_NODES * (N_HID / 4);
    const float4* in4 = (const float4*)input;
    if ((gt & 7) == 0) {                               // one prefetch per 128B line
        for (long long idx = gt; idx < total4; idx += nth)
            asm volatile("prefetch.global.L2 [%0];" :: "l"(in4 + idx));
    }
    grid_barrier(&g_bar1, g);

    // ---- phase 2: gated output (input reads hit L2) ----
    const float b1 = g_b1;
    for (long long idx = gt; idx < total4; idx += nth) {
        int row = (int)(idx >> 6);                     // N_HID/4 == 64
        int c4  = (int)(idx & 63);
        float2 ac = g_aggcnt[row];
        float z = ac.x * rsqrtf(fmaxf(ac.y, 1.0f)) + b1;
        z = fmaxf(z, 0.0f);
        float gate = 1.0f / (1.0f + expf(-z));
        float4 v = in4[idx];
        float4 p = ((const float4*)g_pe_s)[c4];
        float4 o;
        o.x = (v.x + p.x) * gate;
        o.y = (v.y + p.y) * gate;
        o.z = (v.z + p.z) * gate;
        o.w = (v.w + p.w) * gate;
        __stcs(&((float4*)out)[idx], o);               // evict-first write
    }
}

template <typename K, typename... Args>
static inline void launch_pdl(K kern, int grid, int block, Args... args) {
    cudaLaunchConfig_t cfg = {};
    cfg.gridDim = dim3(grid, 1, 1);
    cfg.blockDim = dim3(block, 1, 1);
    cfg.dynamicSmemBytes = 0;
    cfg.stream = 0;
    cudaLaunchAttribute attr[1];
    attr[0].id = cudaLaunchAttributeProgrammaticStreamSerialization;
    attr[0].val.programmaticStreamSerializationAllowed = 1;
    cfg.attrs = attr;
    cfg.numAttrs = 1;
    cudaLaunchKernelEx(&cfg, kern, args...);
}

extern "C" void kernel_launch(void* const* d_in, const int* in_sizes, int n_in,
                              void* d_out, int out_size) {
    const float* input   = (const float*)d_in[0];
    const float* W       = (const float*)d_in[1];
    const float* b       = (const float*)d_in[2];
    const float* pe_coff = (const float*)d_in[3];
    const int*   src     = (const int*)d_in[4];
    const int*   dst     = (const int*)d_in[5];
    const int*   t_ptr   = (const int*)d_in[6];
    float* out = (float*)d_out;

    int n_sm = 148;
    cudaDeviceGetAttribute(&n_sm, cudaDevAttrMultiProcessorCount, 0);
    if (n_sm <= 0) n_sm = 148;

    k_init<<<256, 256>>>(W, b, pe_coff, t_ptr);

    launch_pdl(k_fused, FUSED_GRID, 256, input, src);

    launch_pdl(k_aggout, n_sm, 1024, src, dst, input, out);
}

// round 6
// speedup vs baseline: 1.0928x; 1.0928x over previous
#include <cuda_runtime.h>
#include <cuda_fp16.h>
#include <math.h>

#define N_NODES 100000
#define N_HID   256
#define N_EDGES 3200000

// ---- scratch in device globals (no allocation allowed) ----
__device__ int      g_out_deg[N_NODES];
__device__ float    g_hun[N_NODES];                     // unscaled dot
__device__ unsigned short g_h1h[N_NODES];               // scaled h, fp16 bits
__device__ __align__(4) __half2 g_aggcnt2[N_NODES];     // {agg fp16, count fp16}
__device__ float    g_W1[N_HID];                        // W[:,1]
__device__ float    g_pe_s[N_HID];                      // pe_coff * pe(t+1)
__device__ float    g_pe_dot;
__device__ float    g_b1;

// K0: zero scratch + compute PE row, W1, pe_dot, b1
__global__ void k_init(const float* __restrict__ W,
                       const float* __restrict__ b,
                       const float* __restrict__ pe_coff,
                       const int*   __restrict__ t_ptr) {
    int i = blockIdx.x * blockDim.x + threadIdx.x;
    int stride = gridDim.x * blockDim.x;
    for (int j = i; j < N_NODES; j += stride) {
        g_out_deg[j] = 0;
        ((unsigned*)g_aggcnt2)[j] = 0u;
    }
    if (blockIdx.x == 0) {
        int c = threadIdx.x;               // 256 threads == N_HID
        float w1 = W[c * 2 + 1];
        g_W1[c] = w1;
        int t = *t_ptr;
        float pos  = (float)(t + 1);
        float coff = pe_coff[0];
        int even = c & ~1;
        float div = expf((float)even * (-logf(10000.0f) / (float)N_HID));
        float pe  = (c & 1) ? cosf(pos * div) : sinf(pos * div);
        float pes = coff * pe;
        g_pe_s[c] = pes;
        __shared__ float sred[256];
        sred[c] = pes * w1;
        __syncthreads();
        for (int s = 128; s > 0; s >>= 1) {
            if (c < s) sred[c] += sred[c + s];
            __syncthreads();
        }
        if (c == 0) {
            g_pe_dot = sred[0];
            g_b1 = b[1];
        }
    }
}

// K1 fused: interleaved block roles (1 edge block per 4 node blocks).
#define FUSED_GRID 15625
__global__ void k_fused(const float* __restrict__ input,
                        const int*   __restrict__ src) {
    int b = blockIdx.x;
    if (b % 5 == 0) {
        // ---- edge role: out-degree atomics ----
        int eb = b / 5;
        int i = eb * 256 + threadIdx.x;
        int4 s = make_int4(0, 0, 0, 0);
        bool act = (i < N_EDGES / 4);
        if (act) s = __ldcs(&((const int4*)src)[i]);   // streaming: don't pollute L2
        cudaGridDependencySynchronize();               // k_init zeroed counters
        if (act) {
            atomicAdd(&g_out_deg[s.x], 1);
            atomicAdd(&g_out_deg[s.y], 1);
            atomicAdd(&g_out_deg[s.z], 1);
            atomicAdd(&g_out_deg[s.w], 1);
        }
    } else {
        // ---- node role: unscaled dot(input[r], W1) ----
        int nb = b - (b / 5 + 1);            // 0..12499
        int warp_in_block = threadIdx.x >> 5;
        int lane = threadIdx.x & 31;
        int row = nb * 8 + warp_in_block;
        float4 v0 = make_float4(0, 0, 0, 0), v1 = v0;
        bool act = (row < N_NODES);
        if (act) {
            const float4* rowp = (const float4*)(input + (size_t)row * N_HID);
            v0 = rowp[lane];          // default policy: stays L2-resident for k_out
            v1 = rowp[lane + 32];
        }
        cudaGridDependencySynchronize();               // g_W1 from k_init
        if (act) {
            const float4* w4 = (const float4*)g_W1;
            float4 w0 = w4[lane];
            float4 w1 = w4[lane + 32];
            float acc = v0.x * w0.x + v0.y * w0.y + v0.z * w0.z + v0.w * w0.w
                      + v1.x * w1.x + v1.y * w1.y + v1.z * w1.z + v1.w * w1.w;
#pragma unroll
            for (int o = 16; o > 0; o >>= 1)
                acc += __shfl_xor_sync(0xffffffffu, acc, o);
            if (lane == 0) g_hun[row] = acc;
        }
    }
}

// K2: scale by out-degree norm, store fp16 bits (tiny)
__global__ void k_scale() {
    int i = blockIdx.x * blockDim.x + threadIdx.x;
    cudaGridDependencySynchronize();
    if (i >= N_NODES) return;
    float od = (float)max(g_out_deg[i], 1);
    __half h = __float2half((g_hun[i] + g_pe_dot) * rsqrtf(od));
    g_h1h[i] = __half_as_ushort(h);
}

// K3: persistent edge aggregation. fp16 h table in SMEM; per edge:
//   1 LDS.U16 gather + 1 LOP pack {h, 1.0h} + ONE 32-bit f16x2 RED.
__global__ void __launch_bounds__(1024, 1)
k_agg(const int* __restrict__ src, const int* __restrict__ dst) {
    extern __shared__ unsigned short sh[];   // N_NODES halves = 200000 bytes
    int tid = blockIdx.x * blockDim.x + threadIdx.x;
    int nth = gridDim.x * blockDim.x;
    cudaGridDependencySynchronize();                   // h table ready (k_scale)
    for (int j = threadIdx.x; j < N_NODES / 8; j += blockDim.x)
        ((uint4*)sh)[j] = ((const uint4*)g_h1h)[j];
    __syncthreads();
    const int n4 = N_EDGES / 4;
    for (int i = tid; i < n4; i += nth) {
        int4 s = __ldcs(&((const int4*)src)[i]);
        int4 d = __ldcs(&((const int4*)dst)[i]);
        unsigned p0 = (unsigned)sh[s.x] | 0x3C000000u;   // {h, 1.0h}
        unsigned p1 = (unsigned)sh[s.y] | 0x3C000000u;
        unsigned p2 = (unsigned)sh[s.z] | 0x3C000000u;
        unsigned p3 = (unsigned)sh[s.w] | 0x3C000000u;
#define REDH2(p, v) asm volatile("red.global.add.noftz.f16x2 [%0], %1;" :: "l"(p), "r"(v) : "memory")
        REDH2(&g_aggcnt2[d.x], p0);
        REDH2(&g_aggcnt2[d.y], p1);
        REDH2(&g_aggcnt2[d.z], p2);
        REDH2(&g_aggcnt2[d.w], p3);
#undef REDH2
    }
}

// K4: out[r][c] = (input[r][c] + pe_s[c]) * sigmoid(relu(agg/sqrt(max(cnt,1)) + b1))
__global__ void k_out(const float* __restrict__ input, float* __restrict__ out) {
    long long idx = (long long)blockIdx.x * blockDim.x + threadIdx.x;
    const long long total = (long long)N_NODES * (N_HID / 4);
    bool act = (idx < total);
    float4 v = make_float4(0, 0, 0, 0);
    if (act) v = ((const float4*)input)[idx];          // overlap with k_agg tail
    cudaGridDependencySynchronize();                   // aggcnt final
    if (!act) return;
    int row = (int)(idx >> 6);   // N_HID/4 == 64
    int c4  = (int)(idx & 63);
    __half2 ac = g_aggcnt2[row];
    float agg = __low2float(ac);
    float cnt = __high2float(ac);
    float z = agg * rsqrtf(fmaxf(cnt, 1.0f)) + g_b1;
    z = fmaxf(z, 0.0f);
    float gate = 1.0f / (1.0f + expf(-z));
    float4 p = ((const float4*)g_pe_s)[c4];
    float4 o;
    o.x = (v.x + p.x) * gate;
    o.y = (v.y + p.y) * gate;
    o.z = (v.z + p.z) * gate;
    o.w = (v.w + p.w) * gate;
    __stcs(&((float4*)out)[idx], o);                   // evict-first write
}

template <typename K, typename... Args>
static inline void launch_pdl(K kern, int grid, int block, size_t smem, Args... args) {
    cudaLaunchConfig_t cfg = {};
    cfg.gridDim = dim3(grid, 1, 1);
    cfg.blockDim = dim3(block, 1, 1);
    cfg.dynamicSmemBytes = smem;
    cfg.stream = 0;
    cudaLaunchAttribute attr[1];
    attr[0].id = cudaLaunchAttributeProgrammaticStreamSerialization;
    attr[0].val.programmaticStreamSerializationAllowed = 1;
    cfg.attrs = attr;
    cfg.numAttrs = 1;
    cudaLaunchKernelEx(&cfg, kern, args...);
}

extern "C" void kernel_launch(void* const* d_in, const int* in_sizes, int n_in,
                              void* d_out, int out_size) {
    const float* input   = (const float*)d_in[0];
    const float* W       = (const float*)d_in[1];
    const float* b       = (const float*)d_in[2];
    const float* pe_coff = (const float*)d_in[3];
    const int*   src     = (const int*)d_in[4];
    const int*   dst     = (const int*)d_in[5];
    const int*   t_ptr   = (const int*)d_in[6];
    float* out = (float*)d_out;

    const size_t AGG_SMEM = (size_t)N_NODES * sizeof(unsigned short);  // 200000 B
    cudaFuncSetAttribute(k_agg, cudaFuncAttributeMaxDynamicSharedMemorySize,
                         (int)AGG_SMEM);
    int n_sm = 148;
    cudaDeviceGetAttribute(&n_sm, cudaDevAttrMultiProcessorCount, 0);
    if (n_sm <= 0) n_sm = 148;

    k_init<<<1024, 256>>>(W, b, pe_coff, t_ptr);

    launch_pdl(k_fused, FUSED_GRID, 256, 0, input, src);

    launch_pdl(k_scale, (N_NODES + 255) / 256, 256, 0);

    launch_pdl(k_agg, n_sm, 1024, AGG_SMEM, src, dst);

    {
        long long total = (long long)N_NODES * (N_HID / 4);
        int blocks = (int)((total + 255) / 256);
        launch_pdl(k_out, blocks, 256, 0, input, out);
    }
}

// round 7
// speedup vs baseline: 1.1589x; 1.0605x over previous
#include <cuda_runtime.h>
#include <cuda_fp16.h>
#include <math.h>

#define N_NODES 100000
#define N_HID   256
#define N_EDGES 3200000

// ---- scratch in device globals (no allocation allowed) ----
__device__ int    g_out_deg[N_NODES];
__device__ float  g_hun[N_NODES];                       // unscaled dot
__device__ __half g_h1h[N_NODES];                       // scaled, fp16 (gather table)
__device__ __align__(8) float2 g_aggcnt[N_NODES];       // {agg_sum, in_deg_count}
__device__ float  g_W1[N_HID];                          // W[:,1]
__device__ float  g_pe_s[N_HID];                        // pe_coff * pe(t+1)
__device__ float  g_pe_dot;
__device__ float  g_b1;

// K0: zero scratch + compute PE row, W1, pe_dot, b1.  1024 blocks so each
// thread touches <=1 node element (was latency-bound at 256 blocks: 5.9us).
__global__ void k_init(const float* __restrict__ W,
                       const float* __restrict__ b,
                       const float* __restrict__ pe_coff,
                       const int*   __restrict__ t_ptr) {
    int i = blockIdx.x * blockDim.x + threadIdx.x;
    if (i < N_NODES) {
        g_out_deg[i] = 0;
        g_aggcnt[i]  = make_float2(0.0f, 0.0f);
    }
    if (blockIdx.x == 0) {
        int c = threadIdx.x;               // 256 threads == N_HID
        float w1 = W[c * 2 + 1];
        g_W1[c] = w1;
        int t = *t_ptr;
        float pos  = (float)(t + 1);
        float coff = pe_coff[0];
        int even = c & ~1;
        float div = expf((float)even * (-logf(10000.0f) / (float)N_HID));
        float pe  = (c & 1) ? cosf(pos * div) : sinf(pos * div);
        float pes = coff * pe;
        g_pe_s[c] = pes;
        __shared__ float sred[256];
        sred[c] = pes * w1;
        __syncthreads();
        for (int s = 128; s > 0; s >>= 1) {
            if (c < s) sred[c] += sred[c + s];
            __syncthreads();
        }
        if (c == 0) {
            g_pe_dot = sred[0];
            g_b1 = b[1];
        }
    }
}

// K1 fused: interleaved block roles (1 edge block per 4 node blocks).
#define FUSED_GRID 15625
__global__ void k_fused(const float* __restrict__ input,
                        const int*   __restrict__ src) {
    int b = blockIdx.x;
    if (b % 5 == 0) {
        // ---- edge role: out-degree atomics ----
        int eb = b / 5;
        int i = eb * 256 + threadIdx.x;
        int4 s = make_int4(0, 0, 0, 0);
        bool act = (i < N_EDGES / 4);
        if (act) s = __ldcs(&((const int4*)src)[i]);   // streaming: don't pollute L2
        cudaGridDependencySynchronize();               // k_init zeroed counters
        if (act) {
            atomicAdd(&g_out_deg[s.x], 1);
            atomicAdd(&g_out_deg[s.y], 1);
            atomicAdd(&g_out_deg[s.z], 1);
            atomicAdd(&g_out_deg[s.w], 1);
        }
    } else {
        // ---- node role: unscaled dot(input[r], W1) ----
        int nb = b - (b / 5 + 1);            // 0..12499
        int warp_in_block = threadIdx.x >> 5;
        int lane = threadIdx.x & 31;
        int row = nb * 8 + warp_in_block;
        float4 v0 = make_float4(0, 0, 0, 0), v1 = v0;
        bool act = (row < N_NODES);
        if (act) {
            const float4* rowp = (const float4*)(input + (size_t)row * N_HID);
            v0 = rowp[lane];          // default policy: stays L2-resident for k_out
            v1 = rowp[lane + 32];
        }
        cudaGridDependencySynchronize();               // g_W1 from k_init
        if (act) {
            const float4* w4 = (const float4*)g_W1;
            float4 w0 = w4[lane];
            float4 w1 = w4[lane + 32];
            float acc = v0.x * w0.x + v0.y * w0.y + v0.z * w0.z + v0.w * w0.w
                      + v1.x * w1.x + v1.y * w1.y + v1.z * w1.z + v1.w * w1.w;
#pragma unroll
            for (int o = 16; o > 0; o >>= 1)
                acc += __shfl_xor_sync(0xffffffffu, acc, o);
            if (lane == 0) g_hun[row] = acc;
        }
    }
}

// K2: scale by out-degree norm, store fp16 gather table (tiny)
__global__ void k_scale() {
    int i = blockIdx.x * blockDim.x + threadIdx.x;
    cudaGridDependencySynchronize();
    if (i >= N_NODES) return;
    float od = (float)max(g_out_deg[i], 1);
    g_h1h[i] = __float2half((g_hun[i] + g_pe_dot) * rsqrtf(od));
}

// K3: persistent edge aggregation. fp16 h table in SMEM (LDS gather),
//     one fp32 v2 RED per edge: {h, 1.0} -> {agg, cnt}.
__global__ void __launch_bounds__(1024, 1)
k_agg(const int* __restrict__ src, const int* __restrict__ dst) {
    extern __shared__ __half sh[];   // N_NODES halves = 200000 bytes
    int tid = blockIdx.x * blockDim.x + threadIdx.x;
    int nth = gridDim.x * blockDim.x;
    cudaGridDependencySynchronize();                   // h table ready (k_scale)
    for (int j = threadIdx.x; j < N_NODES / 8; j += blockDim.x)
        ((uint4*)sh)[j] = ((const uint4*)g_h1h)[j];
    __syncthreads();
    const float one = 1.0f;
    const int n4 = N_EDGES / 4;
    for (int i = tid; i < n4; i += nth) {
        int4 s = __ldcs(&((const int4*)src)[i]);
        int4 d = __ldcs(&((const int4*)dst)[i]);
        float h0 = __half2float(sh[s.x]);
        float h1 = __half2float(sh[s.y]);
        float h2 = __half2float(sh[s.z]);
        float h3 = __half2float(sh[s.w]);
#define REDV2(p, h) asm volatile("red.global.add.v2.f32 [%0], {%1, %2};" :: "l"(p), "f"(h), "f"(one) : "memory")
        REDV2(&g_aggcnt[d.x], h0);
        REDV2(&g_aggcnt[d.y], h1);
        REDV2(&g_aggcnt[d.z], h2);
        REDV2(&g_aggcnt[d.w], h3);
#undef REDV2
    }
}

// K4: out[r][c] = (input[r][c] + pe_s[c]) * sigmoid(relu(agg/sqrt(max(cnt,1)) + b1))
__global__ void k_out(const float* __restrict__ input, float* __restrict__ out) {
    long long idx = (long long)blockIdx.x * blockDim.x + threadIdx.x;
    const long long total = (long long)N_NODES * (N_HID / 4);
    bool act = (idx < total);
    float4 v = make_float4(0, 0, 0, 0);
    if (act) v = ((const float4*)input)[idx];          // overlap with k_agg tail (L2 hit)
    cudaGridDependencySynchronize();                   // aggcnt final
    if (!act) return;
    int row = (int)(idx >> 6);   // N_HID/4 == 64
    int c4  = (int)(idx & 63);
    float2 ac = g_aggcnt[row];
    float z = ac.x * rsqrtf(fmaxf(ac.y, 1.0f)) + g_b1;
    z = fmaxf(z, 0.0f);
    float gate = 1.0f / (1.0f + expf(-z));
    float4 p = ((const float4*)g_pe_s)[c4];
    float4 o;
    o.x = (v.x + p.x) * gate;
    o.y = (v.y + p.y) * gate;
    o.z = (v.z + p.z) * gate;
    o.w = (v.w + p.w) * gate;
    __stcs(&((float4*)out)[idx], o);                   // evict-first: keep input in L2
}

template <typename K, typename... Args>
static inline void launch_pdl(K kern, int grid, int block, size_t smem, Args... args) {
    cudaLaunchConfig_t cfg = {};
    cfg.gridDim = dim3(grid, 1, 1);
    cfg.blockDim = dim3(block, 1, 1);
    cfg.dynamicSmemBytes = smem;
    cfg.stream = 0;
    cudaLaunchAttribute attr[1];
    attr[0].id = cudaLaunchAttributeProgrammaticStreamSerialization;
    attr[0].val.programmaticStreamSerializationAllowed = 1;
    cfg.attrs = attr;
    cfg.numAttrs = 1;
    cudaLaunchKernelEx(&cfg, kern, args...);
}

extern "C" void kernel_launch(void* const* d_in, const int* in_sizes, int n_in,
                              void* d_out, int out_size) {
    const float* input   = (const float*)d_in[0];
    const float* W       = (const float*)d_in[1];
    const float* b       = (const float*)d_in[2];
    const float* pe_coff = (const float*)d_in[3];
    const int*   src     = (const int*)d_in[4];
    const int*   dst     = (const int*)d_in[5];
    const int*   t_ptr   = (const int*)d_in[6];
    float* out = (float*)d_out;

    const size_t AGG_SMEM = (size_t)N_NODES * sizeof(__half);   // 200000 B
    cudaFuncSetAttribute(k_agg, cudaFuncAttributeMaxDynamicSharedMemorySize,
                         (int)AGG_SMEM);
    int n_sm = 148;
    cudaDeviceGetAttribute(&n_sm, cudaDevAttrMultiProcessorCount, 0);
    if (n_sm <= 0) n_sm = 148;

    k_init<<<1024, 256>>>(W, b, pe_coff, t_ptr);   // ~2us (was 5.9 at 256 blocks)

    launch_pdl(k_fused, FUSED_GRID, 256, 0, input, src);

    launch_pdl(k_scale, (N_NODES + 255) / 256, 256, 0);

    launch_pdl(k_agg, n_sm, 1024, AGG_SMEM, src, dst);

    {
        long long total = (long long)N_NODES * (N_HID / 4);
        int blocks = (int)((total + 255) / 256);
        launch_pdl(k_out, blocks, 256, 0, input, out);
    }
}

// round 9
// speedup vs baseline: 1.1610x; 1.0018x over previous
#include <cuda_runtime.h>
#include <cuda_fp16.h>
#include <math.h>

#define N_NODES 100000
#define N_HID   256
#define N_EDGES 3200000

// bit-reinterpret helpers (no such builtins in headers)
static __device__ __forceinline__ unsigned h2_to_u32(__half2 h) {
    union { __half2 h; unsigned u; } c; c.h = h; return c.u;
}
static __device__ __forceinline__ __half2 u32_to_h2(unsigned u) {
    union { unsigned u; __half2 h; } c; c.u = u; return c.h;
}

// ---- scratch in device globals (no allocation allowed) ----
__device__ int    g_out_deg[N_NODES];
__device__ float  g_hun[N_NODES];                       // unscaled dot
__device__ __half g_h1h[N_NODES];                       // scaled h, fp16 gather table
__device__ __align__(8) float2 g_aggcnt[N_NODES];       // {agg_sum, in_deg_count}
__device__ __align__(16) __half g_xh[N_NODES * N_HID];  // x = input + pe, fp16 (51.2MB)
__device__ float  g_W1[N_HID];                          // W[:,1]
__device__ float  g_pe_s[N_HID];                        // pe_coff * pe(t+1)
__device__ float  g_pe_dot;
__device__ float  g_b1;

// K0: zero scratch + compute PE row, W1, pe_dot, b1.
__global__ void k_init(const float* __restrict__ W,
                       const float* __restrict__ b,
                       const float* __restrict__ pe_coff,
                       const int*   __restrict__ t_ptr) {
    int i = blockIdx.x * blockDim.x + threadIdx.x;
    if (i < N_NODES) {
        g_out_deg[i] = 0;
        g_aggcnt[i]  = make_float2(0.0f, 0.0f);
    }
    if (blockIdx.x == 0) {
        int c = threadIdx.x;               // 256 threads == N_HID
        float w1 = W[c * 2 + 1];
        g_W1[c] = w1;
        int t = *t_ptr;
        float pos  = (float)(t + 1);
        float coff = pe_coff[0];
        int even = c & ~1;
        float div = expf((float)even * (-logf(10000.0f) / (float)N_HID));
        float pe  = (c & 1) ? cosf(pos * div) : sinf(pos * div);
        float pes = coff * pe;
        g_pe_s[c] = pes;
        __shared__ float sred[256];
        sred[c] = pes * w1;
        __syncthreads();
        for (int s = 128; s > 0; s >>= 1) {
            if (c < s) sred[c] += sred[c + s];
            __syncthreads();
        }
        if (c == 0) {
            g_pe_dot = sred[0];
            g_b1 = b[1];
        }
    }
}

// K1 fused: interleaved block roles (1 edge block per 4 node blocks).
// Node role additionally materializes x = input + pe as fp16 (g_xh) — the
// 51MB write hides under the chip-wide atomic ceiling of the edge role.
#define FUSED_GRID 15625
__global__ void k_fused(const float* __restrict__ input,
                        const int*   __restrict__ src) {
    int b = blockIdx.x;
    if (b % 5 == 0) {
        // ---- edge role: out-degree atomics ----
        int eb = b / 5;
        int i = eb * 256 + threadIdx.x;
        int4 s = make_int4(0, 0, 0, 0);
        bool act = (i < N_EDGES / 4);
        if (act) s = __ldcs(&((const int4*)src)[i]);   // streaming
        cudaGridDependencySynchronize();               // k_init zeroed counters
        if (act) {
            atomicAdd(&g_out_deg[s.x], 1);
            atomicAdd(&g_out_deg[s.y], 1);
            atomicAdd(&g_out_deg[s.z], 1);
            atomicAdd(&g_out_deg[s.w], 1);
        }
    } else {
        // ---- node role: dot(input[r], W1) + write x_h[r] ----
        int nb = b - (b / 5 + 1);            // 0..12499
        int warp_in_block = threadIdx.x >> 5;
        int lane = threadIdx.x & 31;
        int row = nb * 8 + warp_in_block;
        float4 v0 = make_float4(0, 0, 0, 0), v1 = v0;
        bool act = (row < N_NODES);
        if (act) {
            const float4* rowp = (const float4*)(input + (size_t)row * N_HID);
            v0 = __ldcs(&rowp[2 * lane]);       // streaming: input not needed later
            v1 = __ldcs(&rowp[2 * lane + 1]);   // lane covers cols [8*lane, 8*lane+8)
        }
        cudaGridDependencySynchronize();               // g_W1 / g_pe_s from k_init
        if (act) {
            const float4* w4 = (const float4*)g_W1;
            const float4* p4 = (const float4*)g_pe_s;
            float4 w0 = w4[2 * lane];
            float4 w1 = w4[2 * lane + 1];
            float acc = v0.x * w0.x + v0.y * w0.y + v0.z * w0.z + v0.w * w0.w
                      + v1.x * w1.x + v1.y * w1.y + v1.z * w1.z + v1.w * w1.w;
#pragma unroll
            for (int o = 16; o > 0; o >>= 1)
                acc += __shfl_xor_sync(0xffffffffu, acc, o);
            if (lane == 0) g_hun[row] = acc;
            // x_h = fp16(input + pe), 8 halves = one 16B store per lane
            float4 p0 = p4[2 * lane];
            float4 p1 = p4[2 * lane + 1];
            uint4 pk;
            pk.x = h2_to_u32(__floats2half2_rn(v0.x + p0.x, v0.y + p0.y));
            pk.y = h2_to_u32(__floats2half2_rn(v0.z + p0.z, v0.w + p0.w));
            pk.z = h2_to_u32(__floats2half2_rn(v1.x + p1.x, v1.y + p1.y));
            pk.w = h2_to_u32(__floats2half2_rn(v1.z + p1.z, v1.w + p1.w));
            ((uint4*)g_xh)[(size_t)row * 32 + lane] = pk;   // default: L2-resident
        }
    }
}

// K2: scale by out-degree norm, store fp16 gather table (tiny)
__global__ void k_scale() {
    int i = blockIdx.x * blockDim.x + threadIdx.x;
    cudaGridDependencySynchronize();
    if (i >= N_NODES) return;
    float od = (float)max(g_out_deg[i], 1);
    g_h1h[i] = __float2half((g_hun[i] + g_pe_dot) * rsqrtf(od));
}

// K3: persistent edge aggregation. fp16 h table in SMEM (LDS gather),
//     one fp32 v2 RED per edge: {h, 1.0} -> {agg, cnt}.
__global__ void __launch_bounds__(1024, 1)
k_agg(const int* __restrict__ src, const int* __restrict__ dst) {
    extern __shared__ __half sh[];   // N_NODES halves = 200000 bytes
    int tid = blockIdx.x * blockDim.x + threadIdx.x;
    int nth = gridDim.x * blockDim.x;
    cudaGridDependencySynchronize();                   // h table ready (k_scale)
    for (int j = threadIdx.x; j < N_NODES / 8; j += blockDim.x)
        ((uint4*)sh)[j] = ((const uint4*)g_h1h)[j];
    __syncthreads();
    const float one = 1.0f;
    const int n4 = N_EDGES / 4;
    for (int i = tid; i < n4; i += nth) {
        int4 s = __ldcs(&((const int4*)src)[i]);
        int4 d = __ldcs(&((const int4*)dst)[i]);
        float h0 = __half2float(sh[s.x]);
        float h1 = __half2float(sh[s.y]);
        float h2 = __half2float(sh[s.z]);
        float h3 = __half2float(sh[s.w]);
#define REDV2(p, h) asm volatile("red.global.add.v2.f32 [%0], {%1, %2};" :: "l"(p), "f"(h), "f"(one) : "memory")
        REDV2(&g_aggcnt[d.x], h0);
        REDV2(&g_aggcnt[d.y], h1);
        REDV2(&g_aggcnt[d.z], h2);
        REDV2(&g_aggcnt[d.w], h3);
#undef REDV2
    }
}

// K4: out[r][c] = x_h[r][c] * gate(r).  8 floats/thread, 256-bit store.
//     x_h read is L2-resident (51MB); DRAM only sees the 102MB output write.
__global__ void __launch_bounds__(256)
k_out(float* __restrict__ out) {
    int gt = blockIdx.x * blockDim.x + threadIdx.x;
    int nth = gridDim.x * blockDim.x;
    const int total8 = N_NODES * (N_HID / 8);          // 3.2M
    cudaGridDependencySynchronize();                   // aggcnt + x_h final
    const float b1 = g_b1;
    for (int idx = gt; idx < total8; idx += nth) {
        int row = idx >> 5;                            // N_HID/8 == 32
        float2 ac = g_aggcnt[row];
        float z = ac.x * rsqrtf(fmaxf(ac.y, 1.0f)) + b1;
        z = fmaxf(z, 0.0f);
        float gate = 1.0f / (1.0f + expf(-z));
        uint4 pk = __ldg(&((const uint4*)g_xh)[idx]);
        float2 f0 = __half22float2(u32_to_h2(pk.x));
        float2 f1 = __half22float2(u32_to_h2(pk.y));
        float2 f2 = __half22float2(u32_to_h2(pk.z));
        float2 f3 = __half22float2(u32_to_h2(pk.w));
        float o0 = f0.x * gate, o1 = f0.y * gate;
        float o2 = f1.x * gate, o3 = f1.y * gate;
        float o4 = f2.x * gate, o5 = f2.y * gate;
        float o6 = f3.x * gate, o7 = f3.y * gate;
        float* p = out + (size_t)idx * 8;
        asm volatile("st.global.cs.v8.f32 [%0], {%1,%2,%3,%4,%5,%6,%7,%8};"
                     :: "l"(p), "f"(o0), "f"(o1), "f"(o2), "f"(o3),
                        "f"(o4), "f"(o5), "f"(o6), "f"(o7) : "memory");
    }
}

template <typename K, typename... Args>
static inline void launch_pdl(K kern, int grid, int block, size_t smem, Args... args) {
    cudaLaunchConfig_t cfg = {};
    cfg.gridDim = dim3(grid, 1, 1);
    cfg.blockDim = dim3(block, 1, 1);
    cfg.dynamicSmemBytes = smem;
    cfg.stream = 0;
    cudaLaunchAttribute attr[1];
    attr[0].id = cudaLaunchAttributeProgrammaticStreamSerialization;
    attr[0].val.programmaticStreamSerializationAllowed = 1;
    cfg.attrs = attr;
    cfg.numAttrs = 1;
    cudaLaunchKernelEx(&cfg, kern, args...);
}

extern "C" void kernel_launch(void* const* d_in, const int* in_sizes, int n_in,
                              void* d_out, int out_size) {
    const float* input   = (const float*)d_in[0];
    const float* W       = (const float*)d_in[1];
    const float* b       = (const float*)d_in[2];
    const float* pe_coff = (const float*)d_in[3];
    const int*   src     = (const int*)d_in[4];
    const int*   dst     = (const int*)d_in[5];
    const int*   t_ptr   = (const int*)d_in[6];
    float* out = (float*)d_out;

    const size_t AGG_SMEM = (size_t)N_NODES * sizeof(__half);   // 200000 B
    cudaFuncSetAttribute(k_agg, cudaFuncAttributeMaxDynamicSharedMemorySize,
                         (int)AGG_SMEM);
    int n_sm = 148;
    cudaDeviceGetAttribute(&n_sm, cudaDevAttrMultiProcessorCount, 0);
    if (n_sm <= 0) n_sm = 148;

    k_init<<<1024, 256>>>(W, b, pe_coff, t_ptr);

    launch_pdl(k_fused, FUSED_GRID, 256, 0, input, src);

    launch_pdl(k_scale, (N_NODES + 255) / 256, 256, 0);

    launch_pdl(k_agg, n_sm, 1024, AGG_SMEM, src, dst);

    launch_pdl(k_out, n_sm * 8, 256, 0, out);
}